// round 12
// baseline (speedup 1.0000x reference)
#include <cuda_runtime.h>
#include <cuda_fp16.h>
#include <cstdint>

#define BB 2
#define DD 160
#define HH 192
#define WW 160
#define HW (HH*WW)               // 30720
#define DHW (DD*HH*WW)           // 4,915,200
#define NVOX (BB*DD*HH*WW)       // 9,830,400
#define NV4 (NVOX/4)             // 2,457,600
#define INV_WIN3 (1.0f/729.0f)

// ---------------- K1: stats + H box-sum (fp16 ring + prefetch) ----------
#define SEG_H1 12
#define SEGLEN_H1 (HH/SEG_H1)    // 16 (multiple of 8 -> compile-time ring slots)
#define COLS4 (BB*DD*WW/4)       // 12800 float4 columns
#define K1_THREADS (COLS4*SEG_H1)  // 153600
#define K1_BLK 256

// ---------------- K2: D-roll + W-roll + cc + reduce ----------------
#define ROWS2 4
#define SEG_D2 10
#define SEGLEN_D2 (DD/SEG_D2)    // 16
#define HTILES (HH/ROWS2)        // 48
#define K2_BLOCKS (BB*HTILES*SEG_D2)   // 960
#define K2_THREADS 160           // 4 rows x 40 float4-lanes
#define SMROW 42                 // slots per padded row (1 pad + 40 + 1 pad)
#define SMN (ROWS2*SMROW)        // 168 slots per buffer

// Packed fp16 H-summed stats, CHANNEL-INTERLEAVED per element:
//   g_ab[e] = { {s0,s1} for 4 consecutive w }   (4x half2)
//   g_cd[e] = { {s2,s3} for 4 consecutive w }   (4x half2)
//   g_e [e] = { s4 pairs of consecutive w }     (2x half2)
__device__ uint4 g_ab[NV4];
__device__ uint4 g_cd[NV4];
__device__ uint2 g_e [NV4];
__device__ double g_part[K2_BLOCKS];
__device__ int g_sem;            // self-resetting (0 at start of every replay)

__device__ __forceinline__ unsigned int pack2(float a, float b) {
    __half2 h = __floats2half2_rn(a, b);
    return *(unsigned int*)&h;
}
__device__ __forceinline__ float2 unpack2(unsigned int u) {
    __half2 h = *(__half2*)&u;
    return __half22float2(h);
}
__device__ __forceinline__ __half2 u2h(unsigned int u) {
    return *(__half2*)&u;
}
__device__ __forceinline__ unsigned int h2u(__half2 h) {
    return *(unsigned int*)&h;
}
__device__ __forceinline__ uint2 packf4(float4 v) {
    uint2 r; r.x = pack2(v.x, v.y); r.y = pack2(v.z, v.w); return r;
}
__device__ __forceinline__ float4 unpackf4(uint2 u) {
    float2 a = unpack2(u.x), b = unpack2(u.y);
    return make_float4(a.x, a.y, b.x, b.y);
}

__device__ __forceinline__ void acc_add(float4 s[5], float4 i, float4 j) {
    s[0].x+=i.x; s[0].y+=i.y; s[0].z+=i.z; s[0].w+=i.w;
    s[1].x+=j.x; s[1].y+=j.y; s[1].z+=j.z; s[1].w+=j.w;
    s[2].x+=i.x*i.x; s[2].y+=i.y*i.y; s[2].z+=i.z*i.z; s[2].w+=i.w*i.w;
    s[3].x+=j.x*j.x; s[3].y+=j.y*j.y; s[3].z+=j.z*j.z; s[3].w+=j.w*j.w;
    s[4].x+=i.x*j.x; s[4].y+=i.y*j.y; s[4].z+=i.z*j.z; s[4].w+=i.w*j.w;
}
__device__ __forceinline__ void acc_sub(float4 s[5], float4 i, float4 j) {
    s[0].x-=i.x; s[0].y-=i.y; s[0].z-=i.z; s[0].w-=i.w;
    s[1].x-=j.x; s[1].y-=j.y; s[1].z-=j.z; s[1].w-=j.w;
    s[2].x-=i.x*i.x; s[2].y-=i.y*i.y; s[2].z-=i.z*i.z; s[2].w-=i.w*i.w;
    s[3].x-=j.x*j.x; s[3].y-=j.y*j.y; s[3].z-=j.z*j.z; s[3].w-=j.w*j.w;
    s[4].x-=i.x*j.x; s[4].y-=i.y*j.y; s[4].z-=i.z*j.z; s[4].w-=i.w*j.w;
}

// ===========================================================================
// K1: thread = float4 column. Inputs rounded to fp16 at load; ring stores the
// PACKED rounded rows, so rolling add/sub cancels exactly. Output stores are
// channel-interleaved ({s0,s1} / {s2,s3} half2 pairs per element).
// ===========================================================================
__global__ __launch_bounds__(K1_BLK) void stats_h_kernel(
    const float* __restrict__ I, const float* __restrict__ J) {
    int tid = blockIdx.x * K1_BLK + threadIdx.x;
    if (tid >= K1_THREADS) return;
    int col4 = tid % COLS4;
    int seg  = tid / COLS4;
    int b    = col4 / (DD * WW / 4);
    int rest = col4 % (DD * WW / 4);
    int d    = rest / (WW / 4);
    int w4   = rest % (WW / 4);
    const size_t base = (size_t)b * DHW + (size_t)d * HW + (size_t)w4 * 4;
    const int h0 = seg * SEGLEN_H1;   // multiple of 16

    uint2 ringI[8], ringJ[8];
    float4 s[5];
    #pragma unroll
    for (int c = 0; c < 5; ++c) s[c] = make_float4(0.f,0.f,0.f,0.f);

    #pragma unroll
    for (int k = 0; k < 8; ++k) {
        int h = h0 - 4 + k;
        float4 i = make_float4(0.f,0.f,0.f,0.f), j = i;
        if (h >= 0 && h < HH) {
            i = __ldcs((const float4*)&I[base + (size_t)h * WW]);
            j = __ldcs((const float4*)&J[base + (size_t)h * WW]);
        }
        uint2 ip = packf4(i), jp = packf4(j);
        ringI[(k + 4) & 7] = ip;
        ringJ[(k + 4) & 7] = jp;
        acc_add(s, unpackf4(ip), unpackf4(jp));
    }

    // Prefetch the row for the first main step (h0+4).
    float4 pi = make_float4(0.f,0.f,0.f,0.f), pj = pi;
    if (h0 + 4 < HH) {
        pi = __ldcs((const float4*)&I[base + (size_t)(h0 + 4) * WW]);
        pj = __ldcs((const float4*)&J[base + (size_t)(h0 + 4) * WW]);
    }

    for (int hb = h0; hb < h0 + SEGLEN_H1; hb += 8) {
        #pragma unroll
        for (int u = 0; u < 8; ++u) {
            const int slot = (u + 4) & 7;     // == (hb+u+4)&7 since hb%8==0
            int h  = hb + u;
            uint2 nip = packf4(pi), njp = packf4(pj);
            // prefetch next step's row (h+5) — independent, issues early
            int hn = h + 5;
            float4 npi = make_float4(0.f,0.f,0.f,0.f), npj = npi;
            if (hn < HH) {
                npi = __ldcs((const float4*)&I[base + (size_t)hn * WW]);
                npj = __ldcs((const float4*)&J[base + (size_t)hn * WW]);
            }
            acc_add(s, unpackf4(nip), unpackf4(njp));  // window now [h-4,h+4]
            size_t o4 = (base + (size_t)h * WW) >> 2;
            // channel-interleaved packing
            uint4 pab = make_uint4(pack2(s[0].x, s[1].x), pack2(s[0].y, s[1].y),
                                   pack2(s[0].z, s[1].z), pack2(s[0].w, s[1].w));
            uint4 pcd = make_uint4(pack2(s[2].x, s[3].x), pack2(s[2].y, s[3].y),
                                   pack2(s[2].z, s[3].z), pack2(s[2].w, s[3].w));
            uint2 pe  = make_uint2(pack2(s[4].x, s[4].y), pack2(s[4].z, s[4].w));
            __stcs(&g_ab[o4], pab);
            __stcs(&g_cd[o4], pcd);
            __stcs(&g_e [o4], pe);
            acc_sub(s, unpackf4(ringI[slot]), unpackf4(ringJ[slot]));  // exact
            ringI[slot] = nip; ringJ[slot] = njp;
            pi = npi; pj = npj;
        }
    }
}

// ===========================================================================
// K2: rolling D box-sum per float4 column. ch0-3 accumulated ENTIRELY in
// packed half2 channel-pairs (HADD2/HSUB2, no cvt, no repack); ch4 (IJ) in
// fp32. Staged to double-buffered smem (one barrier/step), 9-wide W windows
// on half2 pairs, cc in fp32, global reduction with fused finalize.
// Recurrence: window(dd) = window(dd-1) + row(dd+4) - row(dd-5); prime
// covers [max(0, d0-5), d0+3].
// ===========================================================================
__device__ __forceinline__ float cc1(float s0, float s1, float s2, float s3,
                                     float s4) {
    float cross = fmaf(-s0 * INV_WIN3, s1, s4);
    float Ivar  = fmaf(-s0 * INV_WIN3, s0, s2);
    float Jvar  = fmaf(-s1 * INV_WIN3, s1, s3);
    return __fdividef(cross * cross, fmaf(Ivar, Jvar, 1e-5f));
}

// half2 accumulators: add or subtract one row (ch0-3 packed, ch4 fp32).
__device__ __forceinline__ void load_add_h2(__half2 ab[4], __half2 cd[4],
                                            float4& e, size_t o4, bool add) {
    uint4 vab = __ldcg(&g_ab[o4]);
    uint4 vcd = __ldcg(&g_cd[o4]);
    uint2 ve  = __ldcg(&g_e [o4]);
    if (add) {
        ab[0]=__hadd2(ab[0],u2h(vab.x)); ab[1]=__hadd2(ab[1],u2h(vab.y));
        ab[2]=__hadd2(ab[2],u2h(vab.z)); ab[3]=__hadd2(ab[3],u2h(vab.w));
        cd[0]=__hadd2(cd[0],u2h(vcd.x)); cd[1]=__hadd2(cd[1],u2h(vcd.y));
        cd[2]=__hadd2(cd[2],u2h(vcd.z)); cd[3]=__hadd2(cd[3],u2h(vcd.w));
        float2 p;
        p = unpack2(ve.x); e.x += p.x; e.y += p.y;
        p = unpack2(ve.y); e.z += p.x; e.w += p.y;
    } else {
        ab[0]=__hsub2(ab[0],u2h(vab.x)); ab[1]=__hsub2(ab[1],u2h(vab.y));
        ab[2]=__hsub2(ab[2],u2h(vab.z)); ab[3]=__hsub2(ab[3],u2h(vab.w));
        cd[0]=__hsub2(cd[0],u2h(vcd.x)); cd[1]=__hsub2(cd[1],u2h(vcd.y));
        cd[2]=__hsub2(cd[2],u2h(vcd.z)); cd[3]=__hsub2(cd[3],u2h(vcd.w));
        float2 p;
        p = unpack2(ve.x); e.x -= p.x; e.y -= p.y;
        p = unpack2(ve.y); e.z -= p.x; e.w -= p.y;
    }
}

// Fused diff: acc += row(oa) - row(os). Pure SIMD for ch0-3.
__device__ __forceinline__ void load_diff_h2(__half2 ab[4], __half2 cd[4],
                                             float4& e, size_t oa, size_t os) {
    uint4 Aab = __ldcg(&g_ab[oa]); uint4 Bab = __ldcs(&g_ab[os]);
    uint4 Acd = __ldcg(&g_cd[oa]); uint4 Bcd = __ldcs(&g_cd[os]);
    uint2 Ae  = __ldcg(&g_e [oa]); uint2 Be  = __ldcs(&g_e [os]);
    ab[0]=__hadd2(ab[0],__hsub2(u2h(Aab.x),u2h(Bab.x)));
    ab[1]=__hadd2(ab[1],__hsub2(u2h(Aab.y),u2h(Bab.y)));
    ab[2]=__hadd2(ab[2],__hsub2(u2h(Aab.z),u2h(Bab.z)));
    ab[3]=__hadd2(ab[3],__hsub2(u2h(Aab.w),u2h(Bab.w)));
    cd[0]=__hadd2(cd[0],__hsub2(u2h(Acd.x),u2h(Bcd.x)));
    cd[1]=__hadd2(cd[1],__hsub2(u2h(Acd.y),u2h(Bcd.y)));
    cd[2]=__hadd2(cd[2],__hsub2(u2h(Acd.z),u2h(Bcd.z)));
    cd[3]=__hadd2(cd[3],__hsub2(u2h(Acd.w),u2h(Bcd.w)));
    float2 pa, pb2;
    pa = unpack2(Ae.x); pb2 = unpack2(Be.x);
    e.x += pa.x - pb2.x; e.y += pa.y - pb2.y;
    pa = unpack2(Ae.y); pb2 = unpack2(Be.y);
    e.z += pa.x - pb2.x; e.w += pa.y - pb2.y;
}

// 9-wide windows over 12 half2 values (L=4, own=4, R=4), 2 channels per op.
__device__ __forceinline__ void win_h2(__half2 win[4], uint4 L,
                                       const __half2 own[4], uint4 R) {
    __half2 h0 = u2h(L.x),  h1 = u2h(L.y),  h2 = u2h(L.z),  h3 = u2h(L.w);
    __half2 h4 = own[0], h5 = own[1], h6 = own[2], h7 = own[3];
    __half2 h8 = u2h(R.x),  h9 = u2h(R.y),  h10= u2h(R.z),  h11= u2h(R.w);
    __half2 t = __hadd2(__hadd2(__hadd2(h0, h1), __hadd2(h2, h3)),
                        __hadd2(__hadd2(h4, h5), __hadd2(__hadd2(h6, h7), h8)));
    win[0] = t;
    t = __hadd2(t, __hsub2(h9,  h0)); win[1] = t;
    t = __hadd2(t, __hsub2(h10, h1)); win[2] = t;
    t = __hadd2(t, __hsub2(h11, h2)); win[3] = t;
}

__global__ __launch_bounds__(K2_THREADS) void dwc_kernel(float* __restrict__ out) {
    __shared__ uint4  smAB[2][SMN];            // {s0,s1} half2 x4 per slot
    __shared__ uint4  smCD[2][SMN];            // {s2,s3} half2 x4 per slot
    __shared__ float4 smE [2][SMN];            // s4 fp32
    __shared__ double wsum[K2_THREADS / 32];
    __shared__ bool is_last;

    int bx   = blockIdx.x;
    int dseg = bx % SEG_D2;
    int rest = bx / SEG_D2;
    int htile = rest % HTILES;
    int b     = rest / HTILES;
    int h0 = htile * ROWS2;
    int tid = threadIdx.x;
    int r  = tid / 40;
    int wi = tid % 40;

    // zero everything (pads included; zero bits == zero halves)
    for (int i = tid; i < 2 * SMN; i += K2_THREADS) {
        smAB[0][i] = make_uint4(0u, 0u, 0u, 0u);
        smCD[0][i] = make_uint4(0u, 0u, 0u, 0u);
        smE [0][i] = make_float4(0.f, 0.f, 0.f, 0.f);
    }

    const size_t colbase = (size_t)b * DHW + (size_t)(h0 + r) * WW + wi * 4;
    int d0 = dseg * SEGLEN_D2;

    __half2 ab[4], cd[4];
    __half2 z = __floats2half2_rn(0.f, 0.f);
    #pragma unroll
    for (int k = 0; k < 4; ++k) { ab[k] = z; cd[k] = z; }
    float4 e = make_float4(0.f, 0.f, 0.f, 0.f);

    // Prime: sum rows [max(0, d0-5), d0+3].
    int dp = d0 - 5 > 0 ? d0 - 5 : 0;
    for (int d = dp; d < d0 + 4; ++d)
        load_add_h2(ab, cd, e, (colbase + (size_t)d * HW) >> 2, true);
    __syncthreads();   // pads zeroed before first stage

    const int rb = r * SMROW + wi;   // left slot; own = rb+1; right = rb+2
    float acc = 0.f;
    int pb = 0;
    for (int dd = d0; dd < d0 + SEGLEN_D2; ++dd) {
        int da = dd + 4, ds = dd - 5;
        if (da < DD && ds >= 0) {
            load_diff_h2(ab, cd, e, (colbase + (size_t)da * HW) >> 2,
                                    (colbase + (size_t)ds * HW) >> 2);
        } else {
            if (da < DD) load_add_h2(ab, cd, e, (colbase + (size_t)da * HW) >> 2, true);
            if (ds >= 0) load_add_h2(ab, cd, e, (colbase + (size_t)ds * HW) >> 2, false);
        }

        // stage: bitcast of accumulators (no packing needed)
        uint4 abp = make_uint4(h2u(ab[0]), h2u(ab[1]), h2u(ab[2]), h2u(ab[3]));
        uint4 cdp = make_uint4(h2u(cd[0]), h2u(cd[1]), h2u(cd[2]), h2u(cd[3]));
        smAB[pb][rb + 1] = abp;
        smCD[pb][rb + 1] = cdp;
        smE [pb][rb + 1] = e;
        __syncthreads();   // the ONLY barrier per step (double-buffered)

        __half2 wab[4], wcd[4];
        win_h2(wab, smAB[pb][rb], ab, smAB[pb][rb + 2]);
        win_h2(wcd, smCD[pb][rb], cd, smCD[pb][rb + 2]);

        float wine[4];
        {
            float4 a0 = smE[pb][rb], a2 = smE[pb][rb + 2];
            float f0=a0.x,f1=a0.y,f2=a0.z,f3=a0.w;
            float f4_=e.x,f5=e.y,f6=e.z,f7=e.w;
            float f8=a2.x,f9=a2.y,f10=a2.z,f11=a2.w;
            float t = f0+f1+f2+f3+f4_+f5+f6+f7+f8;
            wine[0] = t;
            t += f9  - f0; wine[1] = t;
            t += f10 - f1; wine[2] = t;
            t += f11 - f2; wine[3] = t;
        }
        #pragma unroll
        for (int k = 0; k < 4; ++k) {
            float2 abf = __half22float2(wab[k]);
            float2 cdf = __half22float2(wcd[k]);
            acc += cc1(abf.x, abf.y, cdf.x, cdf.y, wine[k]);
        }
        pb ^= 1;
    }

    #pragma unroll
    for (int off = 16; off; off >>= 1)
        acc += __shfl_down_sync(0xffffffffu, acc, off);
    int lane = tid & 31, wid = tid >> 5;
    if (lane == 0) wsum[wid] = (double)acc;
    __syncthreads();

    if (tid == 0) {
        double t = 0.0;
        #pragma unroll
        for (int i = 0; i < K2_THREADS / 32; ++i) t += wsum[i];
        g_part[bx] = t;
        __threadfence();
        int v = atomicAdd(&g_sem, 1);
        is_last = (v == gridDim.x - 1);
    }
    __syncthreads();

    if (is_last) {
        __threadfence();
        double t = 0.0;
        for (int i = tid; i < K2_BLOCKS; i += K2_THREADS) t += g_part[i];
        #pragma unroll
        for (int off = 16; off; off >>= 1)
            t += __shfl_down_sync(0xffffffffu, t, off);
        if (lane == 0) wsum[wid] = t;
        __syncthreads();
        if (tid == 0) {
            double tot = 0.0;
            #pragma unroll
            for (int i = 0; i < K2_THREADS / 32; ++i) tot += wsum[i];
            out[0] = (float)(tot / (double)NVOX);
            g_sem = 0;   // reset for next graph replay
        }
    }
}

extern "C" void kernel_launch(void* const* d_in, const int* in_sizes, int n_in,
                              void* d_out, int out_size) {
    const float* I = (const float*)d_in[0];  // predicted
    const float* J = (const float*)d_in[1];  // target

    stats_h_kernel<<<(K1_THREADS + K1_BLK - 1) / K1_BLK, K1_BLK>>>(I, J);
    dwc_kernel<<<K2_BLOCKS, K2_THREADS>>>((float*)d_out);
}

// round 13
// speedup vs baseline: 1.0091x; 1.0091x over previous
#include <cuda_runtime.h>
#include <cuda_fp16.h>
#include <cstdint>

#define BB 2
#define DD 160
#define HH 192
#define WW 160
#define HW (HH*WW)               // 30720
#define DHW (DD*HH*WW)           // 4,915,200
#define NVOX (BB*DD*HH*WW)       // 9,830,400
#define NV4 (NVOX/4)             // 2,457,600
#define INV_WIN3 (1.0f/729.0f)

// ---------------- K1: stats + H box-sum (fp16 ring + prefetch) ----------
#define SEG_H1 12
#define SEGLEN_H1 (HH/SEG_H1)    // 16 (multiple of 8 -> compile-time ring slots)
#define COLS4 (BB*DD*WW/4)       // 12800 float4 columns
#define K1_THREADS (COLS4*SEG_H1)  // 153600
#define K1_BLK 256

// ---------------- K2: D-roll + W-roll + cc + reduce ----------------
#define ROWS2 4
#define SEG_D2 10
#define SEGLEN_D2 (DD/SEG_D2)    // 16
#define HTILES (HH/ROWS2)        // 48
#define K2_BLOCKS (BB*HTILES*SEG_D2)   // 960
#define K2_THREADS 160           // 4 rows x 40 float4-lanes
#define SMROW 42                 // slots per padded row (1 pad + 40 + 1 pad)
#define SMN (ROWS2*SMROW)        // 168 slots per buffer

// Packed fp16 H-summed stats, CHANNEL-INTERLEAVED per element:
//   g_ab[e] = { {s0,s1} for 4 consecutive w }   (4x half2)
//   g_cd[e] = { {s2,s3} for 4 consecutive w }   (4x half2)
//   g_e [e] = { s4 pairs of consecutive w }     (2x half2)
__device__ uint4 g_ab[NV4];
__device__ uint4 g_cd[NV4];
__device__ uint2 g_e [NV4];
__device__ double g_part[K2_BLOCKS];
__device__ int g_sem;            // self-resetting (0 at start of every replay)

__device__ __forceinline__ unsigned int pack2(float a, float b) {
    __half2 h = __floats2half2_rn(a, b);
    return *(unsigned int*)&h;
}
__device__ __forceinline__ float2 unpack2(unsigned int u) {
    __half2 h = *(__half2*)&u;
    return __half22float2(h);
}
__device__ __forceinline__ __half2 u2h(unsigned int u) {
    return *(__half2*)&u;
}
__device__ __forceinline__ unsigned int h2u(__half2 h) {
    return *(unsigned int*)&h;
}
__device__ __forceinline__ uint2 packf4(float4 v) {
    uint2 r; r.x = pack2(v.x, v.y); r.y = pack2(v.z, v.w); return r;
}
__device__ __forceinline__ float4 unpackf4(uint2 u) {
    float2 a = unpack2(u.x), b = unpack2(u.y);
    return make_float4(a.x, a.y, b.x, b.y);
}

__device__ __forceinline__ void acc_add(float4 s[5], float4 i, float4 j) {
    s[0].x+=i.x; s[0].y+=i.y; s[0].z+=i.z; s[0].w+=i.w;
    s[1].x+=j.x; s[1].y+=j.y; s[1].z+=j.z; s[1].w+=j.w;
    s[2].x+=i.x*i.x; s[2].y+=i.y*i.y; s[2].z+=i.z*i.z; s[2].w+=i.w*i.w;
    s[3].x+=j.x*j.x; s[3].y+=j.y*j.y; s[3].z+=j.z*j.z; s[3].w+=j.w*j.w;
    s[4].x+=i.x*j.x; s[4].y+=i.y*j.y; s[4].z+=i.z*j.z; s[4].w+=i.w*j.w;
}
__device__ __forceinline__ void acc_sub(float4 s[5], float4 i, float4 j) {
    s[0].x-=i.x; s[0].y-=i.y; s[0].z-=i.z; s[0].w-=i.w;
    s[1].x-=j.x; s[1].y-=j.y; s[1].z-=j.z; s[1].w-=j.w;
    s[2].x-=i.x*i.x; s[2].y-=i.y*i.y; s[2].z-=i.z*i.z; s[2].w-=i.w*i.w;
    s[3].x-=j.x*j.x; s[3].y-=j.y*j.y; s[3].z-=j.z*j.z; s[3].w-=j.w*j.w;
    s[4].x-=i.x*j.x; s[4].y-=i.y*j.y; s[4].z-=i.z*j.z; s[4].w-=i.w*j.w;
}

// ===========================================================================
// K1: thread = float4 column. Inputs rounded to fp16 at load; ring stores the
// PACKED rounded rows, so rolling add/sub cancels exactly. Output stores are
// channel-interleaved ({s0,s1} / {s2,s3} half2 pairs per element).
// ===========================================================================
__global__ __launch_bounds__(K1_BLK) void stats_h_kernel(
    const float* __restrict__ I, const float* __restrict__ J) {
    int tid = blockIdx.x * K1_BLK + threadIdx.x;
    if (tid >= K1_THREADS) return;
    int col4 = tid % COLS4;
    int seg  = tid / COLS4;
    int b    = col4 / (DD * WW / 4);
    int rest = col4 % (DD * WW / 4);
    int d    = rest / (WW / 4);
    int w4   = rest % (WW / 4);
    const size_t base = (size_t)b * DHW + (size_t)d * HW + (size_t)w4 * 4;
    const int h0 = seg * SEGLEN_H1;   // multiple of 16

    uint2 ringI[8], ringJ[8];
    float4 s[5];
    #pragma unroll
    for (int c = 0; c < 5; ++c) s[c] = make_float4(0.f,0.f,0.f,0.f);

    #pragma unroll
    for (int k = 0; k < 8; ++k) {
        int h = h0 - 4 + k;
        float4 i = make_float4(0.f,0.f,0.f,0.f), j = i;
        if (h >= 0 && h < HH) {
            i = __ldcs((const float4*)&I[base + (size_t)h * WW]);
            j = __ldcs((const float4*)&J[base + (size_t)h * WW]);
        }
        uint2 ip = packf4(i), jp = packf4(j);
        ringI[(k + 4) & 7] = ip;
        ringJ[(k + 4) & 7] = jp;
        acc_add(s, unpackf4(ip), unpackf4(jp));
    }

    // Prefetch the row for the first main step (h0+4).
    float4 pi = make_float4(0.f,0.f,0.f,0.f), pj = pi;
    if (h0 + 4 < HH) {
        pi = __ldcs((const float4*)&I[base + (size_t)(h0 + 4) * WW]);
        pj = __ldcs((const float4*)&J[base + (size_t)(h0 + 4) * WW]);
    }

    for (int hb = h0; hb < h0 + SEGLEN_H1; hb += 8) {
        #pragma unroll
        for (int u = 0; u < 8; ++u) {
            const int slot = (u + 4) & 7;     // == (hb+u+4)&7 since hb%8==0
            int h  = hb + u;
            uint2 nip = packf4(pi), njp = packf4(pj);
            // prefetch next step's row (h+5) — independent, issues early
            int hn = h + 5;
            float4 npi = make_float4(0.f,0.f,0.f,0.f), npj = npi;
            if (hn < HH) {
                npi = __ldcs((const float4*)&I[base + (size_t)hn * WW]);
                npj = __ldcs((const float4*)&J[base + (size_t)hn * WW]);
            }
            acc_add(s, unpackf4(nip), unpackf4(njp));  // window now [h-4,h+4]
            size_t o4 = (base + (size_t)h * WW) >> 2;
            // channel-interleaved packing
            uint4 pab = make_uint4(pack2(s[0].x, s[1].x), pack2(s[0].y, s[1].y),
                                   pack2(s[0].z, s[1].z), pack2(s[0].w, s[1].w));
            uint4 pcd = make_uint4(pack2(s[2].x, s[3].x), pack2(s[2].y, s[3].y),
                                   pack2(s[2].z, s[3].z), pack2(s[2].w, s[3].w));
            uint2 pe  = make_uint2(pack2(s[4].x, s[4].y), pack2(s[4].z, s[4].w));
            __stcs(&g_ab[o4], pab);
            __stcs(&g_cd[o4], pcd);
            __stcs(&g_e [o4], pe);
            acc_sub(s, unpackf4(ringI[slot]), unpackf4(ringJ[slot]));  // exact
            ringI[slot] = nip; ringJ[slot] = njp;
            pi = npi; pj = npj;
        }
    }
}

// ===========================================================================
// K2: rolling D box-sum per float4 column, ch0-3 in packed half2 pairs,
// ch4 fp32. SOFTWARE-PIPELINED: step dd+1's add/sub loads are issued BEFORE
// step dd's __syncthreads, so DRAM latency overlaps barrier + window + cc.
// Recurrence: window(dd) = window(dd-1) + row(dd+4) - row(dd-5); prime
// covers [max(0, d0-5), d0+3].
// ===========================================================================
__device__ __forceinline__ float cc1(float s0, float s1, float s2, float s3,
                                     float s4) {
    float cross = fmaf(-s0 * INV_WIN3, s1, s4);
    float Ivar  = fmaf(-s0 * INV_WIN3, s0, s2);
    float Jvar  = fmaf(-s1 * INV_WIN3, s1, s3);
    return __fdividef(cross * cross, fmaf(Ivar, Jvar, 1e-5f));
}

struct RowLd { uint4 ab, cd; uint2 e; };

__device__ __forceinline__ RowLd ld_row_cg(size_t o4) {
    RowLd r;
    r.ab = __ldcg(&g_ab[o4]);
    r.cd = __ldcg(&g_cd[o4]);
    r.e  = __ldcg(&g_e [o4]);
    return r;
}
__device__ __forceinline__ RowLd ld_row_cs(size_t o4) {
    RowLd r;
    r.ab = __ldcs(&g_ab[o4]);
    r.cd = __ldcs(&g_cd[o4]);
    r.e  = __ldcs(&g_e [o4]);
    return r;
}

__device__ __forceinline__ void apply_add(__half2 ab[4], __half2 cd[4],
                                          float4& e, const RowLd& v) {
    ab[0]=__hadd2(ab[0],u2h(v.ab.x)); ab[1]=__hadd2(ab[1],u2h(v.ab.y));
    ab[2]=__hadd2(ab[2],u2h(v.ab.z)); ab[3]=__hadd2(ab[3],u2h(v.ab.w));
    cd[0]=__hadd2(cd[0],u2h(v.cd.x)); cd[1]=__hadd2(cd[1],u2h(v.cd.y));
    cd[2]=__hadd2(cd[2],u2h(v.cd.z)); cd[3]=__hadd2(cd[3],u2h(v.cd.w));
    float2 p;
    p = unpack2(v.e.x); e.x += p.x; e.y += p.y;
    p = unpack2(v.e.y); e.z += p.x; e.w += p.y;
}
__device__ __forceinline__ void apply_sub(__half2 ab[4], __half2 cd[4],
                                          float4& e, const RowLd& v) {
    ab[0]=__hsub2(ab[0],u2h(v.ab.x)); ab[1]=__hsub2(ab[1],u2h(v.ab.y));
    ab[2]=__hsub2(ab[2],u2h(v.ab.z)); ab[3]=__hsub2(ab[3],u2h(v.ab.w));
    cd[0]=__hsub2(cd[0],u2h(v.cd.x)); cd[1]=__hsub2(cd[1],u2h(v.cd.y));
    cd[2]=__hsub2(cd[2],u2h(v.cd.z)); cd[3]=__hsub2(cd[3],u2h(v.cd.w));
    float2 p;
    p = unpack2(v.e.x); e.x -= p.x; e.y -= p.y;
    p = unpack2(v.e.y); e.z -= p.x; e.w -= p.y;
}

// 9-wide windows over 12 half2 values (L=4, own=4, R=4), 2 channels per op.
__device__ __forceinline__ void win_h2(__half2 win[4], uint4 L,
                                       const __half2 own[4], uint4 R) {
    __half2 h0 = u2h(L.x),  h1 = u2h(L.y),  h2 = u2h(L.z),  h3 = u2h(L.w);
    __half2 h4 = own[0], h5 = own[1], h6 = own[2], h7 = own[3];
    __half2 h8 = u2h(R.x),  h9 = u2h(R.y),  h10= u2h(R.z),  h11= u2h(R.w);
    __half2 t = __hadd2(__hadd2(__hadd2(h0, h1), __hadd2(h2, h3)),
                        __hadd2(__hadd2(h4, h5), __hadd2(__hadd2(h6, h7), h8)));
    win[0] = t;
    t = __hadd2(t, __hsub2(h9,  h0)); win[1] = t;
    t = __hadd2(t, __hsub2(h10, h1)); win[2] = t;
    t = __hadd2(t, __hsub2(h11, h2)); win[3] = t;
}

__global__ __launch_bounds__(K2_THREADS) void dwc_kernel(float* __restrict__ out) {
    __shared__ uint4  smAB[2][SMN];            // {s0,s1} half2 x4 per slot
    __shared__ uint4  smCD[2][SMN];            // {s2,s3} half2 x4 per slot
    __shared__ float4 smE [2][SMN];            // s4 fp32
    __shared__ double wsum[K2_THREADS / 32];
    __shared__ bool is_last;

    int bx   = blockIdx.x;
    int dseg = bx % SEG_D2;
    int rest = bx / SEG_D2;
    int htile = rest % HTILES;
    int b     = rest / HTILES;
    int h0 = htile * ROWS2;
    int tid = threadIdx.x;
    int r  = tid / 40;
    int wi = tid % 40;

    // zero everything (pads included; zero bits == zero halves)
    for (int i = tid; i < 2 * SMN; i += K2_THREADS) {
        smAB[0][i] = make_uint4(0u, 0u, 0u, 0u);
        smCD[0][i] = make_uint4(0u, 0u, 0u, 0u);
        smE [0][i] = make_float4(0.f, 0.f, 0.f, 0.f);
    }

    const size_t colbase = (size_t)b * DHW + (size_t)(h0 + r) * WW + wi * 4;
    int d0 = dseg * SEGLEN_D2;

    __half2 ab[4], cd[4];
    __half2 z = __floats2half2_rn(0.f, 0.f);
    #pragma unroll
    for (int k = 0; k < 4; ++k) { ab[k] = z; cd[k] = z; }
    float4 e = make_float4(0.f, 0.f, 0.f, 0.f);

    // Prime: sum rows [max(0, d0-5), d0+3].
    int dp = d0 - 5 > 0 ? d0 - 5 : 0;
    for (int d = dp; d < d0 + 4; ++d) {
        RowLd v = ld_row_cg((colbase + (size_t)d * HW) >> 2);
        apply_add(ab, cd, e, v);
    }
    __syncthreads();   // pads zeroed before first stage

    const int rb = r * SMROW + wi;   // left slot; own = rb+1; right = rb+2
    float acc = 0.f;
    int pb = 0;

    // Pipelined first loads: step d0 adds row d0+4, subtracts row d0-5.
    bool ha = (d0 + 4) < DD;
    bool hs = (d0 - 5) >= 0;
    RowLd A, S;
    if (ha) A = ld_row_cg((colbase + (size_t)(d0 + 4) * HW) >> 2);
    if (hs) S = ld_row_cs((colbase + (size_t)(d0 - 5) * HW) >> 2);

    for (int dd = d0; dd < d0 + SEGLEN_D2; ++dd) {
        if (ha) apply_add(ab, cd, e, A);
        if (hs) apply_sub(ab, cd, e, S);

        // stage: bitcast of accumulators (no packing needed)
        uint4 abp = make_uint4(h2u(ab[0]), h2u(ab[1]), h2u(ab[2]), h2u(ab[3]));
        uint4 cdp = make_uint4(h2u(cd[0]), h2u(cd[1]), h2u(cd[2]), h2u(cd[3]));
        smAB[pb][rb + 1] = abp;
        smCD[pb][rb + 1] = cdp;
        smE [pb][rb + 1] = e;

        // PREFETCH next step's rows BEFORE the barrier: latency overlaps
        // barrier + window + cc + next update.
        bool last = (dd + 1) == (d0 + SEGLEN_D2);
        bool nha = !last && (dd + 5) < DD;
        bool nhs = !last && (dd - 4) >= 0;
        if (nha) A = ld_row_cg((colbase + (size_t)(dd + 5) * HW) >> 2);
        if (nhs) S = ld_row_cs((colbase + (size_t)(dd - 4) * HW) >> 2);

        __syncthreads();   // the ONLY barrier per step (double-buffered)

        __half2 wab[4], wcd[4];
        win_h2(wab, smAB[pb][rb], ab, smAB[pb][rb + 2]);
        win_h2(wcd, smCD[pb][rb], cd, smCD[pb][rb + 2]);

        float wine[4];
        {
            float4 a0 = smE[pb][rb], a2 = smE[pb][rb + 2];
            float f0=a0.x,f1=a0.y,f2=a0.z,f3=a0.w;
            float f4_=e.x,f5=e.y,f6=e.z,f7=e.w;
            float f8=a2.x,f9=a2.y,f10=a2.z,f11=a2.w;
            float t = f0+f1+f2+f3+f4_+f5+f6+f7+f8;
            wine[0] = t;
            t += f9  - f0; wine[1] = t;
            t += f10 - f1; wine[2] = t;
            t += f11 - f2; wine[3] = t;
        }
        #pragma unroll
        for (int k = 0; k < 4; ++k) {
            float2 abf = __half22float2(wab[k]);
            float2 cdf = __half22float2(wcd[k]);
            acc += cc1(abf.x, abf.y, cdf.x, cdf.y, wine[k]);
        }
        ha = nha; hs = nhs;
        pb ^= 1;
    }

    #pragma unroll
    for (int off = 16; off; off >>= 1)
        acc += __shfl_down_sync(0xffffffffu, acc, off);
    int lane = tid & 31, wid = tid >> 5;
    if (lane == 0) wsum[wid] = (double)acc;
    __syncthreads();

    if (tid == 0) {
        double t = 0.0;
        #pragma unroll
        for (int i = 0; i < K2_THREADS / 32; ++i) t += wsum[i];
        g_part[bx] = t;
        __threadfence();
        int v = atomicAdd(&g_sem, 1);
        is_last = (v == gridDim.x - 1);
    }
    __syncthreads();

    if (is_last) {
        __threadfence();
        double t = 0.0;
        for (int i = tid; i < K2_BLOCKS; i += K2_THREADS) t += g_part[i];
        #pragma unroll
        for (int off = 16; off; off >>= 1)
            t += __shfl_down_sync(0xffffffffu, t, off);
        if (lane == 0) wsum[wid] = t;
        __syncthreads();
        if (tid == 0) {
            double tot = 0.0;
            #pragma unroll
            for (int i = 0; i < K2_THREADS / 32; ++i) tot += wsum[i];
            out[0] = (float)(tot / (double)NVOX);
            g_sem = 0;   // reset for next graph replay
        }
    }
}

extern "C" void kernel_launch(void* const* d_in, const int* in_sizes, int n_in,
                              void* d_out, int out_size) {
    const float* I = (const float*)d_in[0];  // predicted
    const float* J = (const float*)d_in[1];  // target

    stats_h_kernel<<<(K1_THREADS + K1_BLK - 1) / K1_BLK, K1_BLK>>>(I, J);
    dwc_kernel<<<K2_BLOCKS, K2_THREADS>>>((float*)d_out);
}